// round 15
// baseline (speedup 1.0000x reference)
#include <cuda_runtime.h>
#include <cstdint>

// ---------------- static device scratch ----------------
#define MAXN 131072
#define MAXE 2000000

__device__ int    g_deg[MAXN];          // zero at module load; self-cleaned in k_offsets
__device__ float  g_dinv[MAXN];
__device__ float  g_dinv2[MAXN];
__device__ int    g_offs[MAXN + 1];
__device__ int    g_cursor[MAXN];
__device__ int    g_bsum[MAXN / 256 + 2];
__device__ int2   g_csr[MAXE];          // (src, norm-as-int)
__device__ float  g_bufA[(size_t)MAXN * 96];
__device__ float  g_bufB[(size_t)MAXN * 96];
__device__ double g_sum8[8][96];        // zero at load; zeroed by agg24/bnfin each use
__device__ double g_sq8[8][96];
__device__ float  g_scale[96];
__device__ float  g_shift[96];

// ---------------- per-block edge dtype detection ----------------
// int64 edges: high words of the first 256 values are all zero.
__device__ __forceinline__ int detect_is64(const int* __restrict__ p) {
    __shared__ int s64;
    if (threadIdx.x == 0) s64 = 1;
    __syncthreads();
    if (p[2 * threadIdx.x + 1] != 0) s64 = 0;   // benign race; 256 threads
    __syncthreads();
    return s64;
}

// ---------------- preprocessing ----------------
__global__ void k_count(const int* __restrict__ p, int E) {
    int is64 = detect_is64(p);
    int e = blockIdx.x * blockDim.x + threadIdx.x;
    if (e >= E) return;
    int d = is64 ? p[2 * (E + e)] : p[E + e];
    atomicAdd(&g_deg[d], 1);
}

__global__ void k_dinv_bsum(int N) {
    __shared__ int sh[256];
    int t = threadIdx.x;
    int i = blockIdx.x * 256 + t;
    int dg = (i < N) ? g_deg[i] : 0;
    if (i < N) {
        float dt = (float)(dg + 1);   // +1 self-loop
        g_dinv[i]  = rsqrtf(dt);
        g_dinv2[i] = 1.0f / dt;
    }
    sh[t] = dg;
    __syncthreads();
    for (int s = 128; s; s >>= 1) {
        if (t < s) sh[t] += sh[t + s];
        __syncthreads();
    }
    if (t == 0) g_bsum[blockIdx.x] = sh[0];
}

// offsets with inlined cross-block prefix; self-cleans g_deg after last read
__global__ void k_offsets(int N) {
    __shared__ int sh[256];
    __shared__ int red[256];
    int t = threadIdx.x;
    int acc = 0;
    for (int i = t; i < blockIdx.x; i += 256) acc += g_bsum[i];
    red[t] = acc;
    __syncthreads();
    for (int s = 128; s; s >>= 1) {
        if (t < s) red[t] += red[t + s];
        __syncthreads();
    }
    int bpre = red[0];

    int i = blockIdx.x * 256 + t;
    int v = (i < N) ? g_deg[i] : 0;
    sh[t] = v;
    __syncthreads();
    for (int o = 1; o < 256; o <<= 1) {
        int x = (t >= o) ? sh[t - o] : 0;
        __syncthreads();
        sh[t] += x;
        __syncthreads();
    }
    if (i < N) {
        int off = bpre + sh[t] - v;
        g_offs[i]   = off;
        g_cursor[i] = off;
        if (i == N - 1) g_offs[N] = off + v;
        g_deg[i] = 0;               // self-clean for next call
    }
}

__global__ void k_scatter(const int* __restrict__ p, int E) {
    int is64 = detect_is64(p);
    int e = blockIdx.x * blockDim.x + threadIdx.x;
    if (e >= E) return;
    int s, d;
    if (is64) { s = p[2 * e]; d = p[2 * (E + e)]; }
    else      { s = p[e];     d = p[E + e]; }
    int pos = atomicAdd(&g_cursor[d], 1);
    g_csr[pos] = make_int2(s, __float_as_int(g_dinv[s] * g_dinv[d]));
}

// ---------------- layer-1 gather: 4 nodes per warp, 8-lane subgroups ----------------
__global__ __launch_bounds__(256) void k_agg4(
    const float* __restrict__ h, float* __restrict__ out, int N) {
    int wid  = (blockIdx.x * blockDim.x + threadIdx.x) >> 5;
    int lane = threadIdx.x & 31;
    int sub  = lane >> 3;
    int cl   = lane & 7;
    unsigned smask = 0xffu << (sub * 8);
    int gw = wid * 4 + sub;
    const float4* hp = (const float4*)h;
    float4 acc = make_float4(0, 0, 0, 0);
    int beg = 0, end = 0;
    if (gw < N) {
        float4 v = __ldg(hp + (size_t)gw * 8 + cl);
        float w = g_dinv2[gw];
        acc = make_float4(v.x * w, v.y * w, v.z * w, v.w * w);
        beg = g_offs[gw];
        end = g_offs[gw + 1];
    }
    for (int e0 = beg; e0 < end; e0 += 8) {
        int e = e0 + cl;
        int2 ed = (e < end) ? g_csr[e] : make_int2(0, 0);
        int m = end - e0; if (m > 8) m = 8;
        for (int j = 0; j < m; j++) {
            int   s0 = __shfl_sync(smask, ed.x, j, 8);
            float n0 = __int_as_float(__shfl_sync(smask, ed.y, j, 8));
            float4 v0 = __ldg(hp + (size_t)s0 * 8 + cl);
            acc.x = fmaf(n0, v0.x, acc.x); acc.y = fmaf(n0, v0.y, acc.y);
            acc.z = fmaf(n0, v0.z, acc.z); acc.w = fmaf(n0, v0.w, acc.w);
        }
    }
    if (gw < N) ((float4*)out)[(size_t)gw * 8 + cl] = acc;
}

// ---------------- 96-wide gather (warp per node), FFMA2 accumulation ----------------
// Block 0 also zeroes the BN stat shadows for the upcoming GEMM.
__global__ __launch_bounds__(256) void k_agg24(
    const float* __restrict__ h, float* __restrict__ out, int N) {
    if (blockIdx.x == 0) {
        for (int i = threadIdx.x; i < 768; i += 256) {
            ((double*)g_sum8)[i] = 0.0;
            ((double*)g_sq8)[i]  = 0.0;
        }
    }
    int gw   = (blockIdx.x * blockDim.x + threadIdx.x) >> 5;
    int lane = threadIdx.x & 31;
    if (gw >= N) return;
    const ulonglong2* hp = (const ulonglong2*)h;
    bool act = lane < 24;
    unsigned long long a01 = 0ull, a23 = 0ull;
    if (act) {
        ulonglong2 v = __ldg(hp + (size_t)gw * 24 + lane);
        float w = g_dinv2[gw];
        unsigned long long wp;
        asm("mov.b64 %0, {%1, %1};" : "=l"(wp) : "f"(w));
        asm("mul.rn.f32x2 %0, %1, %2;" : "=l"(a01) : "l"(v.x), "l"(wp));
        asm("mul.rn.f32x2 %0, %1, %2;" : "=l"(a23) : "l"(v.y), "l"(wp));
    }
    int beg = g_offs[gw], end = g_offs[gw + 1];
    for (int e0 = beg; e0 < end; e0 += 32) {
        int e = e0 + lane;
        int2 ed = (e < end) ? g_csr[e] : make_int2(0, 0);
        int m = end - e0; if (m > 32) m = 32;
        int j = 0;
        for (; j + 2 <= m; j += 2) {
            int   s0 = __shfl_sync(0xffffffffu, ed.x, j);
            float n0 = __int_as_float(__shfl_sync(0xffffffffu, ed.y, j));
            int   s1 = __shfl_sync(0xffffffffu, ed.x, j + 1);
            float n1 = __int_as_float(__shfl_sync(0xffffffffu, ed.y, j + 1));
            if (act) {
                unsigned long long np0, np1;
                asm("mov.b64 %0, {%1, %1};" : "=l"(np0) : "f"(n0));
                asm("mov.b64 %0, {%1, %1};" : "=l"(np1) : "f"(n1));
                ulonglong2 v0 = __ldg(hp + (size_t)s0 * 24 + lane);
                ulonglong2 v1 = __ldg(hp + (size_t)s1 * 24 + lane);
                asm("fma.rn.f32x2 %0, %1, %2, %0;" : "+l"(a01) : "l"(v0.x), "l"(np0));
                asm("fma.rn.f32x2 %0, %1, %2, %0;" : "+l"(a23) : "l"(v0.y), "l"(np0));
                asm("fma.rn.f32x2 %0, %1, %2, %0;" : "+l"(a01) : "l"(v1.x), "l"(np1));
                asm("fma.rn.f32x2 %0, %1, %2, %0;" : "+l"(a23) : "l"(v1.y), "l"(np1));
            }
        }
        if (j < m) {
            int   s0 = __shfl_sync(0xffffffffu, ed.x, j);
            float n0 = __int_as_float(__shfl_sync(0xffffffffu, ed.y, j));
            if (act) {
                unsigned long long np0;
                asm("mov.b64 %0, {%1, %1};" : "=l"(np0) : "f"(n0));
                ulonglong2 v0 = __ldg(hp + (size_t)s0 * 24 + lane);
                asm("fma.rn.f32x2 %0, %1, %2, %0;" : "+l"(a01) : "l"(v0.x), "l"(np0));
                asm("fma.rn.f32x2 %0, %1, %2, %0;" : "+l"(a23) : "l"(v0.y), "l"(np0));
            }
        }
    }
    if (act) {
        ulonglong2 o; o.x = a01; o.y = a23;
        ((ulonglong2*)out)[(size_t)gw * 24 + lane] = o;
    }
}

// ---------------- GEMM: Y[N,96] = X[N,Fi] @ W[Fi,96] + b, FFMA2, fused BN stats ----------------
__global__ __launch_bounds__(256) void k_gemm96(
    const float* __restrict__ X, const float* __restrict__ W,
    const float* __restrict__ b, float* __restrict__ Y, int N, int Fi) {
    __shared__ float Ws[96 * 96];
    __shared__ float Xt[96 * 32];
    int tid = threadIdx.x;
    int tx = tid & 15, ty = tid >> 4;
    for (int i = tid; i < Fi * 96; i += 256) Ws[i] = W[i];
    int row0 = blockIdx.x * 32;
    for (int i = tid; i < 32 * Fi; i += 256) {
        int r = i & 31, k = i >> 5;
        int row = row0 + r;
        Xt[k * 32 + r] = (row < N) ? X[(size_t)row * Fi + k] : 0.0f;
    }
    __syncthreads();

    unsigned long long acc[2][3] = {{0, 0, 0}, {0, 0, 0}};
    int cb = ty * 6;
    #pragma unroll 4
    for (int k = 0; k < Fi; k++) {
        float2 a2 = *(const float2*)&Xt[k * 32 + 2 * tx];
        unsigned long long p0, p1;
        asm("mov.b64 %0, {%1, %1};" : "=l"(p0) : "f"(a2.x));
        asm("mov.b64 %0, {%1, %1};" : "=l"(p1) : "f"(a2.y));
        const unsigned long long* wrow = (const unsigned long long*)&Ws[k * 96 + cb];
        #pragma unroll
        for (int p = 0; p < 3; p++) {
            unsigned long long w2 = wrow[p];
            asm("fma.rn.f32x2 %0, %1, %2, %0;" : "+l"(acc[0][p]) : "l"(p0), "l"(w2));
            asm("fma.rn.f32x2 %0, %1, %2, %0;" : "+l"(acc[1][p]) : "l"(p1), "l"(w2));
        }
    }

    float bb[6];
    #pragma unroll
    for (int j = 0; j < 6; j++) bb[j] = b[cb + j];
    float ls[6] = {0, 0, 0, 0, 0, 0}, lq[6] = {0, 0, 0, 0, 0, 0};
    #pragma unroll
    for (int rr = 0; rr < 2; rr++) {
        int row = row0 + 2 * tx + rr;
        if (row < N) {
            float v[6];
            #pragma unroll
            for (int p = 0; p < 3; p++)
                asm("mov.b64 {%0, %1}, %2;" : "=f"(v[2 * p]), "=f"(v[2 * p + 1]) : "l"(acc[rr][p]));
            #pragma unroll
            for (int j = 0; j < 6; j++) {
                float val = v[j] + bb[j];
                v[j] = val;
                ls[j] += val; lq[j] += val * val;
            }
            float2* yp = (float2*)&Y[(size_t)row * 96 + cb];
            yp[0] = make_float2(v[0], v[1]);
            yp[1] = make_float2(v[2], v[3]);
            yp[2] = make_float2(v[4], v[5]);
        }
    }

    __syncthreads();
    float* sr = Xt;
    int sh = blockIdx.x & 7;
    #pragma unroll
    for (int j = 0; j < 6; j++) sr[tx * 102 + cb + j] = ls[j];
    __syncthreads();
    for (int st = 8; st; st >>= 1) {
        if (tx < st)
            #pragma unroll
            for (int j = 0; j < 6; j++)
                sr[tx * 102 + cb + j] += sr[(tx + st) * 102 + cb + j];
        __syncthreads();
    }
    if (tx == 0)
        #pragma unroll
        for (int j = 0; j < 6; j++) atomicAdd(&g_sum8[sh][cb + j], (double)sr[cb + j]);
    __syncthreads();
    #pragma unroll
    for (int j = 0; j < 6; j++) sr[tx * 102 + cb + j] = lq[j];
    __syncthreads();
    for (int st = 8; st; st >>= 1) {
        if (tx < st)
            #pragma unroll
            for (int j = 0; j < 6; j++)
                sr[tx * 102 + cb + j] += sr[(tx + st) * 102 + cb + j];
        __syncthreads();
    }
    if (tx == 0)
        #pragma unroll
        for (int j = 0; j < 6; j++) atomicAdd(&g_sq8[sh][cb + j], (double)sr[cb + j]);
}

// layer-3 BN coeffs to global (consumed by gemm_out); zeroes shadows
__global__ void k_bnfin(const float* __restrict__ g, const float* __restrict__ be, int N) {
    int c = threadIdx.x;
    if (c >= 96) return;
    double s = 0.0, q = 0.0;
    #pragma unroll
    for (int i = 0; i < 8; i++) { s += g_sum8[i][c]; q += g_sq8[i][c]; }
    double mu  = s / (double)N;
    double var = q / (double)N - mu * mu;
    if (var < 0.0) var = 0.0;
    float a = g[c] * rsqrtf((float)var + 1e-5f);
    g_scale[c] = a;
    g_shift[c] = be[c] - (float)mu * a;
    #pragma unroll
    for (int i = 0; i < 8; i++) { g_sum8[i][c] = 0.0; g_sq8[i][c] = 0.0; }
}

// BN+ReLU (layers 1-2): coefficients computed in-block from stat shadows
__global__ __launch_bounds__(256) void k_bnrelu(
    const float* __restrict__ X, float* __restrict__ Y,
    const float* __restrict__ g, const float* __restrict__ be, int N) {
    __shared__ float sc[96], sf[96];
    int t = threadIdx.x;
    if (t < 96) {
        double s = 0.0, q = 0.0;
        #pragma unroll
        for (int i = 0; i < 8; i++) { s += g_sum8[i][t]; q += g_sq8[i][t]; }
        double mu  = s / (double)N;
        double var = q / (double)N - mu * mu;
        if (var < 0.0) var = 0.0;
        float a = g[t] * rsqrtf((float)var + 1e-5f);
        sc[t] = a;
        sf[t] = be[t] - (float)mu * a;
    }
    __syncthreads();
    int total4 = N * 24;
    for (int i = blockIdx.x * 256 + t; i < total4; i += gridDim.x * 256) {
        int c = (i % 24) * 4;
        float4 v = ((const float4*)X)[i];
        v.x = fmaxf(fmaf(v.x, sc[c],     sf[c]),     0.f);
        v.y = fmaxf(fmaf(v.y, sc[c + 1], sf[c + 1]), 0.f);
        v.z = fmaxf(fmaf(v.z, sc[c + 2], sf[c + 2]), 0.f);
        v.w = fmaxf(fmaf(v.w, sc[c + 3], sf[c + 3]), 0.f);
        ((float4*)Y)[i] = v;
    }
}

// ---------------- final projection, 2 rows/warp (16-lane subgroups) ----------------
__global__ __launch_bounds__(256) void k_gemm_out(
    const float* __restrict__ X, const float* __restrict__ W,
    float* __restrict__ T, int N) {
    __shared__ float Ws[192];
    int tid = threadIdx.x;
    if (tid < 192) Ws[tid] = W[tid];
    __syncthreads();
    int wid = tid >> 5, lane = tid & 31;
    int half = lane >> 4, hl = lane & 15;
    int row = (blockIdx.x * 8 + wid) * 2 + half;
    if (row >= N) return;
    float s0 = 0.0f, s1 = 0.0f;
    #pragma unroll
    for (int k0 = 0; k0 < 96; k0 += 16) {
        int c = k0 + hl;
        float x = X[(size_t)row * 96 + c];
        x = fmaxf(fmaf(x, g_scale[c], g_shift[c]), 0.f);
        s0 += x * Ws[c * 2];
        s1 += x * Ws[c * 2 + 1];
    }
    #pragma unroll
    for (int o = 8; o; o >>= 1) {
        s0 += __shfl_down_sync(0xffffffffu, s0, o, 16);
        s1 += __shfl_down_sync(0xffffffffu, s1, o, 16);
    }
    if (hl == 0) { T[(size_t)row * 2] = s0; T[(size_t)row * 2 + 1] = s1; }
}

// ---------------- final width-2 aggregation, 4 nodes/warp (8-lane subgroups) ----------------
__global__ __launch_bounds__(256) void k_aggf(
    const float* __restrict__ T, const float* __restrict__ b4,
    float* __restrict__ out, int N) {
    int wid  = (blockIdx.x * blockDim.x + threadIdx.x) >> 5;
    int lane = threadIdx.x & 31;
    int sub  = lane >> 3, cl = lane & 7;
    int gw = wid * 4 + sub;
    int beg = 0, end = 0;
    if (gw < N) { beg = g_offs[gw]; end = g_offs[gw + 1]; }
    float a0 = 0.f, a1 = 0.f;
    for (int e = beg + cl; e < end; e += 8) {
        int2 ed = g_csr[e];
        float2 v = __ldg((const float2*)T + ed.x);
        float nm = __int_as_float(ed.y);
        a0 = fmaf(nm, v.x, a0);
        a1 = fmaf(nm, v.y, a1);
    }
    #pragma unroll
    for (int o = 4; o; o >>= 1) {
        a0 += __shfl_down_sync(0xffffffffu, a0, o, 8);
        a1 += __shfl_down_sync(0xffffffffu, a1, o, 8);
    }
    if (gw < N && cl == 0) {
        float2 t = ((const float2*)T)[gw];
        float w = g_dinv2[gw];
        out[2 * gw]     = b4[0] + t.x * w + a0;
        out[2 * gw + 1] = b4[1] + t.y * w + a1;
    }
}

// ---------------- host ----------------
static inline int cdiv(int a, int b) { return (a + b - 1) / b; }

extern "C" void kernel_launch(void* const* d_in, const int* in_sizes, int n_in,
                              void* d_out, int out_size) {
    const float* x  = (const float*)d_in[0];
    const int*   ei = (const int*)d_in[1];
    const float* W1 = (const float*)d_in[2];  const float* b1 = (const float*)d_in[3];
    const float* g1 = (const float*)d_in[4];  const float* be1 = (const float*)d_in[5];
    const float* W2 = (const float*)d_in[6];  const float* b2 = (const float*)d_in[7];
    const float* g2 = (const float*)d_in[8];  const float* be2 = (const float*)d_in[9];
    const float* W3 = (const float*)d_in[10]; const float* b3 = (const float*)d_in[11];
    const float* g3 = (const float*)d_in[12]; const float* be3 = (const float*)d_in[13];
    const float* W4 = (const float*)d_in[14]; const float* b4 = (const float*)d_in[15];
    float* out = (float*)d_out;

    int E   = in_sizes[1] / 2;
    int H   = in_sizes[3];           // 96
    int Fin = in_sizes[2] / H;       // 32
    int N   = in_sizes[0] / Fin;     // 50000
    (void)n_in; (void)out_size;

    void *pA = nullptr, *pB = nullptr;
    cudaGetSymbolAddress(&pA, g_bufA);
    cudaGetSymbolAddress(&pB, g_bufB);
    float* bufA = (float*)pA;
    float* bufB = (float*)pB;

    int nb = cdiv(N, 256);
    int gemmGrid = cdiv(N, 32);
    int aggGrid  = cdiv(N, 8);

    // -------- per-call graph preprocessing (deg/stats self-clean each call) --------
    k_count    <<<cdiv(E, 256), 256>>>(ei, E);
    k_dinv_bsum<<<nb, 256>>>(N);
    k_offsets  <<<nb, 256>>>(N);
    k_scatter  <<<cdiv(E, 256), 256>>>(ei, E);

    // -------- layer 1 --------
    k_agg4<<<cdiv(N, 32), 256>>>(x, bufA, N);
    k_gemm96<<<gemmGrid, 256>>>(bufA, W1, b1, bufB, N, Fin);
    k_bnrelu<<<1024, 256>>>(bufB, bufB, g1, be1, N);

    // -------- layer 2 --------
    k_agg24<<<aggGrid, 256>>>(bufB, bufA, N);     // block 0 zeroes stat shadows
    k_gemm96<<<gemmGrid, 256>>>(bufA, W2, b2, bufB, N, 96);
    k_bnrelu<<<1024, 256>>>(bufB, bufB, g2, be2, N);

    // -------- layer 3 --------
    k_agg24<<<aggGrid, 256>>>(bufB, bufA, N);     // block 0 zeroes stat shadows
    k_gemm96<<<gemmGrid, 256>>>(bufA, W3, b3, bufB, N, 96);
    k_bnfin<<<1, 96>>>(g3, be3, N);

    // -------- layer 4 --------
    k_gemm_out<<<cdiv(N, 16), 256>>>(bufB, W4, bufA, N);
    k_aggf<<<cdiv(N, 32), 256>>>(bufA, b4, out, N);
}

// round 16
// speedup vs baseline: 1.1278x; 1.1278x over previous
#include <cuda_runtime.h>
#include <cstdint>

// ---------------- static device scratch ----------------
#define MAXN 131072
#define MAXE 2000000

__device__ int    g_flag64;
__device__ int    g_deg[MAXN];
__device__ float  g_dinv[MAXN];
__device__ float  g_dinv2[MAXN];
__device__ int    g_offs[MAXN + 1];
__device__ int    g_cursor[MAXN];
__device__ int    g_bsum[MAXN / 256 + 2];
__device__ int    g_bpre[MAXN / 256 + 2];
__device__ int2   g_csr[MAXE];          // (src, norm-as-int)
__device__ float  g_bufA[(size_t)MAXN * 96];
__device__ float  g_bufB[(size_t)MAXN * 96];
__device__ double g_sum8[8][96];
__device__ double g_sq8[8][96];
__device__ float  g_scale[96];
__device__ float  g_shift[96];

// ---------------- init: dtype detect + zero degrees + zero stats ----------------
__global__ void k_init(const int* __restrict__ p, int N) {
    int i = blockIdx.x * blockDim.x + threadIdx.x;
    if (i < N) g_deg[i] = 0;
    if (i < 8 * 96) { ((double*)g_sum8)[i] = 0.0; ((double*)g_sq8)[i] = 0.0; }
    if (blockIdx.x == 0) {
        int v = p[2 * threadIdx.x + 1];
        unsigned any = __ballot_sync(0xffffffffu, v != 0);
        __shared__ int s;
        if (threadIdx.x == 0) s = 0;
        __syncthreads();
        if (any && (threadIdx.x % 32 == 0)) atomicOr(&s, 1);
        __syncthreads();
        if (threadIdx.x == 0) g_flag64 = (s == 0) ? 1 : 0;
    }
}

__global__ void k_count(const int* __restrict__ p, int E) {
    int e = blockIdx.x * blockDim.x + threadIdx.x;
    if (e >= E) return;
    int d = g_flag64 ? p[2 * (E + e)] : p[E + e];
    atomicAdd(&g_deg[d], 1);
}

__global__ void k_dinv_bsum(int N) {
    __shared__ int sh[256];
    int t = threadIdx.x;
    int i = blockIdx.x * 256 + t;
    int dg = (i < N) ? g_deg[i] : 0;
    if (i < N) {
        float dt = (float)(dg + 1);   // +1 self-loop
        g_dinv[i]  = rsqrtf(dt);
        g_dinv2[i] = 1.0f / dt;
    }
    sh[t] = dg;
    __syncthreads();
    for (int s = 128; s; s >>= 1) {
        if (t < s) sh[t] += sh[t + s];
        __syncthreads();
    }
    if (t == 0) g_bsum[blockIdx.x] = sh[0];
}

__global__ void k_bscan(int nb) {   // single block, 512 threads
    __shared__ int sh[512];
    int t = threadIdx.x;
    int v = (t < nb) ? g_bsum[t] : 0;
    sh[t] = v;
    __syncthreads();
    for (int o = 1; o < 512; o <<= 1) {
        int x = (t >= o) ? sh[t - o] : 0;
        __syncthreads();
        sh[t] += x;
        __syncthreads();
    }
    if (t < nb) g_bpre[t] = sh[t] - v;  // exclusive
}

__global__ void k_offsets(int N) {
    __shared__ int sh[256];
    int t = threadIdx.x;
    int i = blockIdx.x * 256 + t;
    int v = (i < N) ? g_deg[i] : 0;
    sh[t] = v;
    __syncthreads();
    for (int o = 1; o < 256; o <<= 1) {
        int x = (t >= o) ? sh[t - o] : 0;
        __syncthreads();
        sh[t] += x;
        __syncthreads();
    }
    if (i < N) {
        int off = g_bpre[blockIdx.x] + sh[t] - v;
        g_offs[i]   = off;
        g_cursor[i] = off;
        if (i == N - 1) g_offs[N] = off + v;
    }
}

__global__ void k_scatter(const int* __restrict__ p, int E) {
    int e = blockIdx.x * blockDim.x + threadIdx.x;
    if (e >= E) return;
    int s, d;
    if (g_flag64) { s = p[2 * e]; d = p[2 * (E + e)]; }
    else          { s = p[e];     d = p[E + e]; }
    int pos = atomicAdd(&g_cursor[d], 1);
    g_csr[pos] = make_int2(s, __float_as_int(g_dinv[s] * g_dinv[d]));
}

// ---------------- layer-1 gather: 4 nodes per warp, 8-lane subgroups ----------------
__global__ __launch_bounds__(256) void k_agg4(
    const float* __restrict__ h, float* __restrict__ out, int N) {
    int wid  = (blockIdx.x * blockDim.x + threadIdx.x) >> 5;
    int lane = threadIdx.x & 31;
    int sub  = lane >> 3;
    int cl   = lane & 7;
    unsigned smask = 0xffu << (sub * 8);
    int gw = wid * 4 + sub;
    const float4* hp = (const float4*)h;
    float4 acc = make_float4(0, 0, 0, 0);
    int beg = 0, end = 0;
    if (gw < N) {
        float4 v = __ldg(hp + (size_t)gw * 8 + cl);
        float w = g_dinv2[gw];
        acc = make_float4(v.x * w, v.y * w, v.z * w, v.w * w);
        beg = g_offs[gw];
        end = g_offs[gw + 1];
    }
    for (int e0 = beg; e0 < end; e0 += 8) {
        int e = e0 + cl;
        int2 ed = (e < end) ? g_csr[e] : make_int2(0, 0);
        int m = end - e0; if (m > 8) m = 8;
        for (int j = 0; j < m; j++) {
            int   s0 = __shfl_sync(smask, ed.x, j, 8);
            float n0 = __int_as_float(__shfl_sync(smask, ed.y, j, 8));
            float4 v0 = __ldg(hp + (size_t)s0 * 8 + cl);
            acc.x = fmaf(n0, v0.x, acc.x); acc.y = fmaf(n0, v0.y, acc.y);
            acc.z = fmaf(n0, v0.z, acc.z); acc.w = fmaf(n0, v0.w, acc.w);
        }
    }
    if (gw < N) ((float4*)out)[(size_t)gw * 8 + cl] = acc;
}

// ---------------- 96-wide gather (warp per node), FFMA2 accumulation ----------------
__global__ __launch_bounds__(256) void k_agg24(
    const float* __restrict__ h, float* __restrict__ out, int N) {
    int gw   = (blockIdx.x * blockDim.x + threadIdx.x) >> 5;
    int lane = threadIdx.x & 31;
    if (gw >= N) return;
    const ulonglong2* hp = (const ulonglong2*)h;
    bool act = lane < 24;
    unsigned long long a01 = 0ull, a23 = 0ull;
    if (act) {
        ulonglong2 v = __ldg(hp + (size_t)gw * 24 + lane);
        float w = g_dinv2[gw];
        unsigned long long wp;
        asm("mov.b64 %0, {%1, %1};" : "=l"(wp) : "f"(w));
        asm("mul.rn.f32x2 %0, %1, %2;" : "=l"(a01) : "l"(v.x), "l"(wp));
        asm("mul.rn.f32x2 %0, %1, %2;" : "=l"(a23) : "l"(v.y), "l"(wp));
    }
    int beg = g_offs[gw], end = g_offs[gw + 1];
    for (int e0 = beg; e0 < end; e0 += 32) {
        int e = e0 + lane;
        int2 ed = (e < end) ? g_csr[e] : make_int2(0, 0);
        int m = end - e0; if (m > 32) m = 32;
        int j = 0;
        for (; j + 2 <= m; j += 2) {
            int   s0 = __shfl_sync(0xffffffffu, ed.x, j);
            float n0 = __int_as_float(__shfl_sync(0xffffffffu, ed.y, j));
            int   s1 = __shfl_sync(0xffffffffu, ed.x, j + 1);
            float n1 = __int_as_float(__shfl_sync(0xffffffffu, ed.y, j + 1));
            if (act) {
                unsigned long long np0, np1;
                asm("mov.b64 %0, {%1, %1};" : "=l"(np0) : "f"(n0));
                asm("mov.b64 %0, {%1, %1};" : "=l"(np1) : "f"(n1));
                ulonglong2 v0 = __ldg(hp + (size_t)s0 * 24 + lane);
                ulonglong2 v1 = __ldg(hp + (size_t)s1 * 24 + lane);
                asm("fma.rn.f32x2 %0, %1, %2, %0;" : "+l"(a01) : "l"(v0.x), "l"(np0));
                asm("fma.rn.f32x2 %0, %1, %2, %0;" : "+l"(a23) : "l"(v0.y), "l"(np0));
                asm("fma.rn.f32x2 %0, %1, %2, %0;" : "+l"(a01) : "l"(v1.x), "l"(np1));
                asm("fma.rn.f32x2 %0, %1, %2, %0;" : "+l"(a23) : "l"(v1.y), "l"(np1));
            }
        }
        if (j < m) {
            int   s0 = __shfl_sync(0xffffffffu, ed.x, j);
            float n0 = __int_as_float(__shfl_sync(0xffffffffu, ed.y, j));
            if (act) {
                unsigned long long np0;
                asm("mov.b64 %0, {%1, %1};" : "=l"(np0) : "f"(n0));
                ulonglong2 v0 = __ldg(hp + (size_t)s0 * 24 + lane);
                asm("fma.rn.f32x2 %0, %1, %2, %0;" : "+l"(a01) : "l"(v0.x), "l"(np0));
                asm("fma.rn.f32x2 %0, %1, %2, %0;" : "+l"(a23) : "l"(v0.y), "l"(np0));
            }
        }
    }
    if (act) {
        ulonglong2 o; o.x = a01; o.y = a23;
        ((ulonglong2*)out)[(size_t)gw * 24 + lane] = o;
    }
}

// ---------------- GEMM: Y[N,96] = X[N,Fi] @ W[Fi,96] + b, FFMA2, fused BN stats ----------------
// Coalesced X staging with XOR swizzle: Xt[k*32 + (r ^ (k&30))].
__global__ __launch_bounds__(256) void k_gemm96(
    const float* __restrict__ X, const float* __restrict__ W,
    const float* __restrict__ b, float* __restrict__ Y, int N, int Fi) {
    __shared__ float Ws[96 * 96];
    __shared__ float Xt[96 * 32];
    int tid = threadIdx.x;
    int tx = tid & 15, ty = tid >> 4;
    for (int i = tid; i < Fi * 96; i += 256) Ws[i] = W[i];
    int row0 = blockIdx.x * 32;
    for (int i = tid; i < 32 * Fi; i += 256) {
        int r = i / Fi;            // row within tile
        int k = i - r * Fi;        // k fastest -> coalesced global read
        int row = row0 + r;
        Xt[k * 32 + (r ^ (k & 30))] = (row < N) ? X[(size_t)row * Fi + k] : 0.0f;
    }
    __syncthreads();

    unsigned long long acc[2][3] = {{0, 0, 0}, {0, 0, 0}};
    int cb = ty * 6;
    #pragma unroll 4
    for (int k = 0; k < Fi; k++) {
        float2 a2 = *(const float2*)&Xt[k * 32 + ((2 * tx) ^ (k & 30))];
        unsigned long long p0, p1;
        asm("mov.b64 %0, {%1, %1};" : "=l"(p0) : "f"(a2.x));
        asm("mov.b64 %0, {%1, %1};" : "=l"(p1) : "f"(a2.y));
        const unsigned long long* wrow = (const unsigned long long*)&Ws[k * 96 + cb];
        #pragma unroll
        for (int p = 0; p < 3; p++) {
            unsigned long long w2 = wrow[p];
            asm("fma.rn.f32x2 %0, %1, %2, %0;" : "+l"(acc[0][p]) : "l"(p0), "l"(w2));
            asm("fma.rn.f32x2 %0, %1, %2, %0;" : "+l"(acc[1][p]) : "l"(p1), "l"(w2));
        }
    }

    float bb[6];
    #pragma unroll
    for (int j = 0; j < 6; j++) bb[j] = b[cb + j];
    float ls[6] = {0, 0, 0, 0, 0, 0}, lq[6] = {0, 0, 0, 0, 0, 0};
    #pragma unroll
    for (int rr = 0; rr < 2; rr++) {
        int row = row0 + 2 * tx + rr;
        if (row < N) {
            float v[6];
            #pragma unroll
            for (int p = 0; p < 3; p++)
                asm("mov.b64 {%0, %1}, %2;" : "=f"(v[2 * p]), "=f"(v[2 * p + 1]) : "l"(acc[rr][p]));
            #pragma unroll
            for (int j = 0; j < 6; j++) {
                float val = v[j] + bb[j];
                v[j] = val;
                ls[j] += val; lq[j] += val * val;
            }
            float2* yp = (float2*)&Y[(size_t)row * 96 + cb];
            yp[0] = make_float2(v[0], v[1]);
            yp[1] = make_float2(v[2], v[3]);
            yp[2] = make_float2(v[4], v[5]);
        }
    }

    // stats reduction over the 16 tx slots per column (pad 102 -> conflict-free)
    __syncthreads();
    float* sr = Xt;
    int sh = blockIdx.x & 7;
    #pragma unroll
    for (int j = 0; j < 6; j++) sr[tx * 102 + cb + j] = ls[j];
    __syncthreads();
    for (int st = 8; st; st >>= 1) {
        if (tx < st)
            #pragma unroll
            for (int j = 0; j < 6; j++)
                sr[tx * 102 + cb + j] += sr[(tx + st) * 102 + cb + j];
        __syncthreads();
    }
    if (tx == 0)
        #pragma unroll
        for (int j = 0; j < 6; j++) atomicAdd(&g_sum8[sh][cb + j], (double)sr[cb + j]);
    __syncthreads();
    #pragma unroll
    for (int j = 0; j < 6; j++) sr[tx * 102 + cb + j] = lq[j];
    __syncthreads();
    for (int st = 8; st; st >>= 1) {
        if (tx < st)
            #pragma unroll
            for (int j = 0; j < 6; j++)
                sr[tx * 102 + cb + j] += sr[(tx + st) * 102 + cb + j];
        __syncthreads();
    }
    if (tx == 0)
        #pragma unroll
        for (int j = 0; j < 6; j++) atomicAdd(&g_sq8[sh][cb + j], (double)sr[cb + j]);
}

// finalize BN coefficients, then zero the shadow accumulators for the next layer
__global__ void k_bnfin(const float* __restrict__ g, const float* __restrict__ be, int N) {
    int c = threadIdx.x;
    if (c >= 96) return;
    double s = 0.0, q = 0.0;
    #pragma unroll
    for (int i = 0; i < 8; i++) { s += g_sum8[i][c]; q += g_sq8[i][c]; }
    double mu  = s / (double)N;
    double var = q / (double)N - mu * mu;
    if (var < 0.0) var = 0.0;
    float a = g[c] * rsqrtf((float)var + 1e-5f);
    g_scale[c] = a;
    g_shift[c] = be[c] - (float)mu * a;
    #pragma unroll
    for (int i = 0; i < 8; i++) { g_sum8[i][c] = 0.0; g_sq8[i][c] = 0.0; }
}

// elementwise BN+ReLU (applied once per node, not per edge)
__global__ void k_bnrelu(const float* __restrict__ X, float* __restrict__ Y, int total4) {
    int t = blockIdx.x * blockDim.x + threadIdx.x;
    if (t >= total4) return;
    int c = t % 24;
    float4 sc = ((const float4*)g_scale)[c];
    float4 sf = ((const float4*)g_shift)[c];
    float4 v = ((const float4*)X)[t];
    v.x = fmaxf(fmaf(v.x, sc.x, sf.x), 0.f);
    v.y = fmaxf(fmaf(v.y, sc.y, sf.y), 0.f);
    v.z = fmaxf(fmaf(v.z, sc.z, sf.z), 0.f);
    v.w = fmaxf(fmaf(v.w, sc.w, sf.w), 0.f);
    ((float4*)Y)[t] = v;
}

// ---------------- final projection, 2 rows/warp (16-lane subgroups) ----------------
__global__ __launch_bounds__(256) void k_gemm_out(
    const float* __restrict__ X, const float* __restrict__ W,
    float* __restrict__ T, int N) {
    __shared__ float Ws[192];
    int tid = threadIdx.x;
    if (tid < 192) Ws[tid] = W[tid];
    __syncthreads();
    int wid = tid >> 5, lane = tid & 31;
    int half = lane >> 4, hl = lane & 15;
    int row = (blockIdx.x * 8 + wid) * 2 + half;
    if (row >= N) return;
    float s0 = 0.0f, s1 = 0.0f;
    #pragma unroll
    for (int k0 = 0; k0 < 96; k0 += 16) {
        int c = k0 + hl;
        float x = X[(size_t)row * 96 + c];
        x = fmaxf(fmaf(x, g_scale[c], g_shift[c]), 0.f);
        s0 += x * Ws[c * 2];
        s1 += x * Ws[c * 2 + 1];
    }
    #pragma unroll
    for (int o = 8; o; o >>= 1) {
        s0 += __shfl_down_sync(0xffffffffu, s0, o, 16);
        s1 += __shfl_down_sync(0xffffffffu, s1, o, 16);
    }
    if (hl == 0) { T[(size_t)row * 2] = s0; T[(size_t)row * 2 + 1] = s1; }
}

// ---------------- final width-2 aggregation, 4 nodes/warp (8-lane subgroups) ----------------
__global__ __launch_bounds__(256) void k_aggf(
    const float* __restrict__ T, const float* __restrict__ b4,
    float* __restrict__ out, int N) {
    int wid  = (blockIdx.x * blockDim.x + threadIdx.x) >> 5;
    int lane = threadIdx.x & 31;
    int sub  = lane >> 3, cl = lane & 7;
    int gw = wid * 4 + sub;
    int beg = 0, end = 0;
    if (gw < N) { beg = g_offs[gw]; end = g_offs[gw + 1]; }
    float a0 = 0.f, a1 = 0.f;
    for (int e = beg + cl; e < end; e += 8) {
        int2 ed = g_csr[e];
        float2 v = __ldg((const float2*)T + ed.x);
        float nm = __int_as_float(ed.y);
        a0 = fmaf(nm, v.x, a0);
        a1 = fmaf(nm, v.y, a1);
    }
    #pragma unroll
    for (int o = 4; o; o >>= 1) {
        a0 += __shfl_down_sync(0xffffffffu, a0, o, 8);
        a1 += __shfl_down_sync(0xffffffffu, a1, o, 8);
    }
    if (gw < N && cl == 0) {
        float2 t = ((const float2*)T)[gw];
        float w = g_dinv2[gw];
        out[2 * gw]     = b4[0] + t.x * w + a0;
        out[2 * gw + 1] = b4[1] + t.y * w + a1;
    }
}

// ---------------- host ----------------
static inline int cdiv(int a, int b) { return (a + b - 1) / b; }

extern "C" void kernel_launch(void* const* d_in, const int* in_sizes, int n_in,
                              void* d_out, int out_size) {
    const float* x  = (const float*)d_in[0];
    const int*   ei = (const int*)d_in[1];
    const float* W1 = (const float*)d_in[2];  const float* b1 = (const float*)d_in[3];
    const float* g1 = (const float*)d_in[4];  const float* be1 = (const float*)d_in[5];
    const float* W2 = (const float*)d_in[6];  const float* b2 = (const float*)d_in[7];
    const float* g2 = (const float*)d_in[8];  const float* be2 = (const float*)d_in[9];
    const float* W3 = (const float*)d_in[10]; const float* b3 = (const float*)d_in[11];
    const float* g3 = (const float*)d_in[12]; const float* be3 = (const float*)d_in[13];
    const float* W4 = (const float*)d_in[14]; const float* b4 = (const float*)d_in[15];
    float* out = (float*)d_out;

    int E   = in_sizes[1] / 2;
    int H   = in_sizes[3];           // 96
    int Fin = in_sizes[2] / H;       // 32
    int N   = in_sizes[0] / Fin;     // 50000
    (void)n_in; (void)out_size;

    void *pA = nullptr, *pB = nullptr;
    cudaGetSymbolAddress(&pA, g_bufA);
    cudaGetSymbolAddress(&pB, g_bufB);
    float* bufA = (float*)pA;
    float* bufB = (float*)pB;

    int nb = cdiv(N, 256);
    int gemmGrid = cdiv(N, 32);
    int aggGrid  = cdiv(N, 8);

    // -------- per-call graph preprocessing: degrees, norms, CSR --------
    k_init     <<<nb, 256>>>(ei, N);
    k_count    <<<cdiv(E, 256), 256>>>(ei, E);
    k_dinv_bsum<<<nb, 256>>>(N);
    k_bscan    <<<1, 512>>>(nb);
    k_offsets  <<<nb, 256>>>(N);
    k_scatter  <<<cdiv(E, 256), 256>>>(ei, E);

    // -------- layer 1 --------
    k_agg4<<<cdiv(N, 32), 256>>>(x, bufA, N);
    k_gemm96<<<gemmGrid, 256>>>(bufA, W1, b1, bufB, N, Fin);
    k_bnfin<<<1, 96>>>(g1, be1, N);
    k_bnrelu<<<cdiv(N * 24, 256), 256>>>(bufB, bufB, N * 24);

    // -------- layer 2 --------
    k_agg24<<<aggGrid, 256>>>(bufB, bufA, N);
    k_gemm96<<<gemmGrid, 256>>>(bufA, W2, b2, bufB, N, 96);
    k_bnfin<<<1, 96>>>(g2, be2, N);
    k_bnrelu<<<cdiv(N * 24, 256), 256>>>(bufB, bufB, N * 24);

    // -------- layer 3 --------
    k_agg24<<<aggGrid, 256>>>(bufB, bufA, N);
    k_gemm96<<<gemmGrid, 256>>>(bufA, W3, b3, bufB, N, 96);
    k_bnfin<<<1, 96>>>(g3, be3, N);

    // -------- layer 4 --------
    k_gemm_out<<<cdiv(N, 16), 256>>>(bufB, W4, bufA, N);
    k_aggf<<<cdiv(N, 32), 256>>>(bufA, b4, out, N);
}

// round 17
// speedup vs baseline: 1.3108x; 1.1623x over previous
#include <cuda_runtime.h>
#include <cstdint>

// ---------------- static device scratch ----------------
#define MAXN 131072
#define MAXE 2000000

__device__ int    g_flag64;
__device__ int    g_deg[MAXN];
__device__ float  g_dinv[MAXN];
__device__ float  g_dinv2[MAXN];
__device__ int    g_offs[MAXN + 1];
__device__ int    g_cursor[MAXN];
__device__ int    g_bsum[MAXN / 256 + 2];
__device__ int    g_bpre[MAXN / 256 + 2];
__device__ int2   g_csr[MAXE];          // (src, norm-as-int)
__device__ float  g_bufA[(size_t)MAXN * 96];
__device__ float  g_bufB[(size_t)MAXN * 96];
__device__ double g_sum8[8][96];
__device__ double g_sq8[8][96];
__device__ float  g_scale[96];
__device__ float  g_shift[96];

// ---------------- init: dtype detect + zero degrees + zero stats ----------------
__global__ void k_init(const int* __restrict__ p, int N) {
    int i = blockIdx.x * blockDim.x + threadIdx.x;
    if (i < N) g_deg[i] = 0;
    if (i < 8 * 96) { ((double*)g_sum8)[i] = 0.0; ((double*)g_sq8)[i] = 0.0; }
    if (blockIdx.x == 0) {
        int v = p[2 * threadIdx.x + 1];
        unsigned any = __ballot_sync(0xffffffffu, v != 0);
        __shared__ int s;
        if (threadIdx.x == 0) s = 0;
        __syncthreads();
        if (any && (threadIdx.x % 32 == 0)) atomicOr(&s, 1);
        __syncthreads();
        if (threadIdx.x == 0) g_flag64 = (s == 0) ? 1 : 0;
    }
}

__global__ void k_count(const int* __restrict__ p, int E) {
    int e = blockIdx.x * blockDim.x + threadIdx.x;
    if (e >= E) return;
    int d = g_flag64 ? p[2 * (E + e)] : p[E + e];
    atomicAdd(&g_deg[d], 1);
}

__global__ void k_dinv_bsum(int N) {
    __shared__ int sh[256];
    int t = threadIdx.x;
    int i = blockIdx.x * 256 + t;
    int dg = (i < N) ? g_deg[i] : 0;
    if (i < N) {
        float dt = (float)(dg + 1);   // +1 self-loop
        g_dinv[i]  = rsqrtf(dt);
        g_dinv2[i] = 1.0f / dt;
    }
    sh[t] = dg;
    __syncthreads();
    for (int s = 128; s; s >>= 1) {
        if (t < s) sh[t] += sh[t + s];
        __syncthreads();
    }
    if (t == 0) g_bsum[blockIdx.x] = sh[0];
}

__global__ void k_bscan(int nb) {   // single block, 512 threads
    __shared__ int sh[512];
    int t = threadIdx.x;
    int v = (t < nb) ? g_bsum[t] : 0;
    sh[t] = v;
    __syncthreads();
    for (int o = 1; o < 512; o <<= 1) {
        int x = (t >= o) ? sh[t - o] : 0;
        __syncthreads();
        sh[t] += x;
        __syncthreads();
    }
    if (t < nb) g_bpre[t] = sh[t] - v;  // exclusive
}

__global__ void k_offsets(int N) {
    __shared__ int sh[256];
    int t = threadIdx.x;
    int i = blockIdx.x * 256 + t;
    int v = (i < N) ? g_deg[i] : 0;
    sh[t] = v;
    __syncthreads();
    for (int o = 1; o < 256; o <<= 1) {
        int x = (t >= o) ? sh[t - o] : 0;
        __syncthreads();
        sh[t] += x;
        __syncthreads();
    }
    if (i < N) {
        int off = g_bpre[blockIdx.x] + sh[t] - v;
        g_offs[i]   = off;
        g_cursor[i] = off;
        if (i == N - 1) g_offs[N] = off + v;
    }
}

__global__ void k_scatter(const int* __restrict__ p, int E) {
    int e = blockIdx.x * blockDim.x + threadIdx.x;
    if (e >= E) return;
    int s, d;
    if (g_flag64) { s = p[2 * e]; d = p[2 * (E + e)]; }
    else          { s = p[e];     d = p[E + e]; }
    int pos = atomicAdd(&g_cursor[d], 1);
    g_csr[pos] = make_int2(s, __float_as_int(g_dinv[s] * g_dinv[d]));
}

// ---------------- layer-1 gather: 4 nodes per warp, 8-lane subgroups ----------------
__global__ __launch_bounds__(256) void k_agg4(
    const float* __restrict__ h, float* __restrict__ out, int N) {
    int wid  = (blockIdx.x * blockDim.x + threadIdx.x) >> 5;
    int lane = threadIdx.x & 31;
    int sub  = lane >> 3;
    int cl   = lane & 7;
    unsigned smask = 0xffu << (sub * 8);
    int gw = wid * 4 + sub;
    const float4* hp = (const float4*)h;
    float4 acc = make_float4(0, 0, 0, 0);
    int beg = 0, end = 0;
    if (gw < N) {
        float4 v = __ldg(hp + (size_t)gw * 8 + cl);
        float w = g_dinv2[gw];
        acc = make_float4(v.x * w, v.y * w, v.z * w, v.w * w);
        beg = g_offs[gw];
        end = g_offs[gw + 1];
    }
    for (int e0 = beg; e0 < end; e0 += 8) {
        int e = e0 + cl;
        int2 ed = (e < end) ? g_csr[e] : make_int2(0, 0);
        int m = end - e0; if (m > 8) m = 8;
        for (int j = 0; j < m; j++) {
            int   s0 = __shfl_sync(smask, ed.x, j, 8);
            float n0 = __int_as_float(__shfl_sync(smask, ed.y, j, 8));
            float4 v0 = __ldg(hp + (size_t)s0 * 8 + cl);
            acc.x = fmaf(n0, v0.x, acc.x); acc.y = fmaf(n0, v0.y, acc.y);
            acc.z = fmaf(n0, v0.z, acc.z); acc.w = fmaf(n0, v0.w, acc.w);
        }
    }
    if (gw < N) ((float4*)out)[(size_t)gw * 8 + cl] = acc;
}

// ---------------- 96-wide gather (warp per node), FFMA2 accumulation ----------------
__global__ __launch_bounds__(256) void k_agg24(
    const float* __restrict__ h, float* __restrict__ out, int N) {
    int gw   = (blockIdx.x * blockDim.x + threadIdx.x) >> 5;
    int lane = threadIdx.x & 31;
    if (gw >= N) return;
    const ulonglong2* hp = (const ulonglong2*)h;
    bool act = lane < 24;
    unsigned long long a01 = 0ull, a23 = 0ull;
    if (act) {
        ulonglong2 v = __ldg(hp + (size_t)gw * 24 + lane);
        float w = g_dinv2[gw];
        unsigned long long wp;
        asm("mov.b64 %0, {%1, %1};" : "=l"(wp) : "f"(w));
        asm("mul.rn.f32x2 %0, %1, %2;" : "=l"(a01) : "l"(v.x), "l"(wp));
        asm("mul.rn.f32x2 %0, %1, %2;" : "=l"(a23) : "l"(v.y), "l"(wp));
    }
    int beg = g_offs[gw], end = g_offs[gw + 1];
    for (int e0 = beg; e0 < end; e0 += 32) {
        int e = e0 + lane;
        int2 ed = (e < end) ? g_csr[e] : make_int2(0, 0);
        int m = end - e0; if (m > 32) m = 32;
        int j = 0;
        for (; j + 2 <= m; j += 2) {
            int   s0 = __shfl_sync(0xffffffffu, ed.x, j);
            float n0 = __int_as_float(__shfl_sync(0xffffffffu, ed.y, j));
            int   s1 = __shfl_sync(0xffffffffu, ed.x, j + 1);
            float n1 = __int_as_float(__shfl_sync(0xffffffffu, ed.y, j + 1));
            if (act) {
                unsigned long long np0, np1;
                asm("mov.b64 %0, {%1, %1};" : "=l"(np0) : "f"(n0));
                asm("mov.b64 %0, {%1, %1};" : "=l"(np1) : "f"(n1));
                ulonglong2 v0 = __ldg(hp + (size_t)s0 * 24 + lane);
                ulonglong2 v1 = __ldg(hp + (size_t)s1 * 24 + lane);
                asm("fma.rn.f32x2 %0, %1, %2, %0;" : "+l"(a01) : "l"(v0.x), "l"(np0));
                asm("fma.rn.f32x2 %0, %1, %2, %0;" : "+l"(a23) : "l"(v0.y), "l"(np0));
                asm("fma.rn.f32x2 %0, %1, %2, %0;" : "+l"(a01) : "l"(v1.x), "l"(np1));
                asm("fma.rn.f32x2 %0, %1, %2, %0;" : "+l"(a23) : "l"(v1.y), "l"(np1));
            }
        }
        if (j < m) {
            int   s0 = __shfl_sync(0xffffffffu, ed.x, j);
            float n0 = __int_as_float(__shfl_sync(0xffffffffu, ed.y, j));
            if (act) {
                unsigned long long np0;
                asm("mov.b64 %0, {%1, %1};" : "=l"(np0) : "f"(n0));
                ulonglong2 v0 = __ldg(hp + (size_t)s0 * 24 + lane);
                asm("fma.rn.f32x2 %0, %1, %2, %0;" : "+l"(a01) : "l"(v0.x), "l"(np0));
                asm("fma.rn.f32x2 %0, %1, %2, %0;" : "+l"(a23) : "l"(v0.y), "l"(np0));
            }
        }
    }
    if (act) {
        ulonglong2 o; o.x = a01; o.y = a23;
        ((ulonglong2*)out)[(size_t)gw * 24 + lane] = o;
    }
}

// ---------------- GEMM: Y[N,96] = X[N,Fi] @ W[Fi,96] + b, FFMA2, fused BN stats ----------------
// Coalesced X staging (XOR swizzle) + coalesced Y writes:
// rg = tid>>4 owns rows {2rg, 2rg+1}; l = tid&15 owns col-pair chunks {l, l+16, l+32}.
__global__ __launch_bounds__(256) void k_gemm96(
    const float* __restrict__ X, const float* __restrict__ W,
    const float* __restrict__ b, float* __restrict__ Y, int N, int Fi) {
    __shared__ float Ws[96 * 96];
    __shared__ float Xt[96 * 32];
    int tid = threadIdx.x;
    int rg = tid >> 4;          // row group: rows 2rg, 2rg+1
    int l  = tid & 15;          // col-chunk lane: chunks l, l+16, l+32 (8B each)
    for (int i = tid; i < Fi * 96; i += 256) Ws[i] = W[i];
    int row0 = blockIdx.x * 32;
    for (int i = tid; i < 32 * Fi; i += 256) {
        int r = i / Fi;            // row within tile
        int k = i - r * Fi;        // k fastest -> coalesced global read
        int row = row0 + r;
        Xt[k * 32 + (r ^ (k & 30))] = (row < N) ? X[(size_t)row * Fi + k] : 0.0f;
    }
    __syncthreads();

    unsigned long long acc[2][3] = {{0, 0, 0}, {0, 0, 0}};
    #pragma unroll 4
    for (int k = 0; k < Fi; k++) {
        float2 a2 = *(const float2*)&Xt[k * 32 + ((2 * rg) ^ (k & 30))];
        unsigned long long p0, p1;
        asm("mov.b64 %0, {%1, %1};" : "=l"(p0) : "f"(a2.x));
        asm("mov.b64 %0, {%1, %1};" : "=l"(p1) : "f"(a2.y));
        const unsigned long long* wk = (const unsigned long long*)&Ws[k * 96];
        #pragma unroll
        for (int p = 0; p < 3; p++) {
            unsigned long long w2 = wk[l + 16 * p];
            asm("fma.rn.f32x2 %0, %1, %2, %0;" : "+l"(acc[0][p]) : "l"(p0), "l"(w2));
            asm("fma.rn.f32x2 %0, %1, %2, %0;" : "+l"(acc[1][p]) : "l"(p1), "l"(w2));
        }
    }

    float bb[6];
    #pragma unroll
    for (int p = 0; p < 3; p++) {
        int col = 2 * (l + 16 * p);
        bb[2 * p]     = b[col];
        bb[2 * p + 1] = b[col + 1];
    }
    float ls[6] = {0, 0, 0, 0, 0, 0}, lq[6] = {0, 0, 0, 0, 0, 0};
    #pragma unroll
    for (int rr = 0; rr < 2; rr++) {
        int row = row0 + 2 * rg + rr;
        if (row < N) {
            float v[6];
            #pragma unroll
            for (int p = 0; p < 3; p++)
                asm("mov.b64 {%0, %1}, %2;" : "=f"(v[2 * p]), "=f"(v[2 * p + 1]) : "l"(acc[rr][p]));
            #pragma unroll
            for (int j = 0; j < 6; j++) {
                float val = v[j] + bb[j];
                v[j] = val;
                ls[j] += val; lq[j] += val * val;
            }
            // coalesced: 16 lanes write 8B at 8B stride = 128B contiguous per STG.64
            unsigned long long* yrow = (unsigned long long*)&Y[(size_t)row * 96];
            #pragma unroll
            for (int p = 0; p < 3; p++) {
                unsigned long long pk;
                asm("mov.b64 %0, {%1, %2};" : "=l"(pk) : "f"(v[2 * p]), "f"(v[2 * p + 1]));
                yrow[l + 16 * p] = pk;
            }
        }
    }

    // stats reduction over the 16 row-groups (pad 102)
    __syncthreads();
    float* sr = Xt;
    int sh = blockIdx.x & 7;
    #pragma unroll
    for (int p = 0; p < 3; p++) {
        int col = 2 * (l + 16 * p);
        sr[rg * 102 + col]     = ls[2 * p];
        sr[rg * 102 + col + 1] = ls[2 * p + 1];
    }
    __syncthreads();
    for (int st = 8; st; st >>= 1) {
        if (rg < st)
            #pragma unroll
            for (int p = 0; p < 3; p++) {
                int col = 2 * (l + 16 * p);
                sr[rg * 102 + col]     += sr[(rg + st) * 102 + col];
                sr[rg * 102 + col + 1] += sr[(rg + st) * 102 + col + 1];
            }
        __syncthreads();
    }
    if (rg == 0)
        #pragma unroll
        for (int p = 0; p < 3; p++) {
            int col = 2 * (l + 16 * p);
            atomicAdd(&g_sum8[sh][col],     (double)sr[col]);
            atomicAdd(&g_sum8[sh][col + 1], (double)sr[col + 1]);
        }
    __syncthreads();
    #pragma unroll
    for (int p = 0; p < 3; p++) {
        int col = 2 * (l + 16 * p);
        sr[rg * 102 + col]     = lq[2 * p];
        sr[rg * 102 + col + 1] = lq[2 * p + 1];
    }
    __syncthreads();
    for (int st = 8; st; st >>= 1) {
        if (rg < st)
            #pragma unroll
            for (int p = 0; p < 3; p++) {
                int col = 2 * (l + 16 * p);
                sr[rg * 102 + col]     += sr[(rg + st) * 102 + col];
                sr[rg * 102 + col + 1] += sr[(rg + st) * 102 + col + 1];
            }
        __syncthreads();
    }
    if (rg == 0)
        #pragma unroll
        for (int p = 0; p < 3; p++) {
            int col = 2 * (l + 16 * p);
            atomicAdd(&g_sq8[sh][col],     (double)sr[col]);
            atomicAdd(&g_sq8[sh][col + 1], (double)sr[col + 1]);
        }
}

// finalize BN coefficients, then zero the shadow accumulators for the next layer
__global__ void k_bnfin(const float* __restrict__ g, const float* __restrict__ be, int N) {
    int c = threadIdx.x;
    if (c >= 96) return;
    double s = 0.0, q = 0.0;
    #pragma unroll
    for (int i = 0; i < 8; i++) { s += g_sum8[i][c]; q += g_sq8[i][c]; }
    double mu  = s / (double)N;
    double var = q / (double)N - mu * mu;
    if (var < 0.0) var = 0.0;
    float a = g[c] * rsqrtf((float)var + 1e-5f);
    g_scale[c] = a;
    g_shift[c] = be[c] - (float)mu * a;
    #pragma unroll
    for (int i = 0; i < 8; i++) { g_sum8[i][c] = 0.0; g_sq8[i][c] = 0.0; }
}

// elementwise BN+ReLU (applied once per node, not per edge)
__global__ void k_bnrelu(const float* __restrict__ X, float* __restrict__ Y, int total4) {
    int t = blockIdx.x * blockDim.x + threadIdx.x;
    if (t >= total4) return;
    int c = t % 24;
    float4 sc = ((const float4*)g_scale)[c];
    float4 sf = ((const float4*)g_shift)[c];
    float4 v = ((const float4*)X)[t];
    v.x = fmaxf(fmaf(v.x, sc.x, sf.x), 0.f);
    v.y = fmaxf(fmaf(v.y, sc.y, sf.y), 0.f);
    v.z = fmaxf(fmaf(v.z, sc.z, sf.z), 0.f);
    v.w = fmaxf(fmaf(v.w, sc.w, sf.w), 0.f);
    ((float4*)Y)[t] = v;
}

// ---------------- final projection, 2 rows/warp (16-lane subgroups) ----------------
__global__ __launch_bounds__(256) void k_gemm_out(
    const float* __restrict__ X, const float* __restrict__ W,
    float* __restrict__ T, int N) {
    __shared__ float Ws[192];
    int tid = threadIdx.x;
    if (tid < 192) Ws[tid] = W[tid];
    __syncthreads();
    int wid = tid >> 5, lane = tid & 31;
    int half = lane >> 4, hl = lane & 15;
    int row = (blockIdx.x * 8 + wid) * 2 + half;
    if (row >= N) return;
    float s0 = 0.0f, s1 = 0.0f;
    #pragma unroll
    for (int k0 = 0; k0 < 96; k0 += 16) {
        int c = k0 + hl;
        float x = X[(size_t)row * 96 + c];
        x = fmaxf(fmaf(x, g_scale[c], g_shift[c]), 0.f);
        s0 += x * Ws[c * 2];
        s1 += x * Ws[c * 2 + 1];
    }
    #pragma unroll
    for (int o = 8; o; o >>= 1) {
        s0 += __shfl_down_sync(0xffffffffu, s0, o, 16);
        s1 += __shfl_down_sync(0xffffffffu, s1, o, 16);
    }
    if (hl == 0) { T[(size_t)row * 2] = s0; T[(size_t)row * 2 + 1] = s1; }
}

// ---------------- final width-2 aggregation, 4 nodes/warp (8-lane subgroups) ----------------
__global__ __launch_bounds__(256) void k_aggf(
    const float* __restrict__ T, const float* __restrict__ b4,
    float* __restrict__ out, int N) {
    int wid  = (blockIdx.x * blockDim.x + threadIdx.x) >> 5;
    int lane = threadIdx.x & 31;
    int sub  = lane >> 3, cl = lane & 7;
    int gw = wid * 4 + sub;
    int beg = 0, end = 0;
    if (gw < N) { beg = g_offs[gw]; end = g_offs[gw + 1]; }
    float a0 = 0.f, a1 = 0.f;
    for (int e = beg + cl; e < end; e += 8) {
        int2 ed = g_csr[e];
        float2 v = __ldg((const float2*)T + ed.x);
        float nm = __int_as_float(ed.y);
        a0 = fmaf(nm, v.x, a0);
        a1 = fmaf(nm, v.y, a1);
    }
    #pragma unroll
    for (int o = 4; o; o >>= 1) {
        a0 += __shfl_down_sync(0xffffffffu, a0, o, 8);
        a1 += __shfl_down_sync(0xffffffffu, a1, o, 8);
    }
    if (gw < N && cl == 0) {
        float2 t = ((const float2*)T)[gw];
        float w = g_dinv2[gw];
        out[2 * gw]     = b4[0] + t.x * w + a0;
        out[2 * gw + 1] = b4[1] + t.y * w + a1;
    }
}

// ---------------- host ----------------
static inline int cdiv(int a, int b) { return (a + b - 1) / b; }

extern "C" void kernel_launch(void* const* d_in, const int* in_sizes, int n_in,
                              void* d_out, int out_size) {
    const float* x  = (const float*)d_in[0];
    const int*   ei = (const int*)d_in[1];
    const float* W1 = (const float*)d_in[2];  const float* b1 = (const float*)d_in[3];
    const float* g1 = (const float*)d_in[4];  const float* be1 = (const float*)d_in[5];
    const float* W2 = (const float*)d_in[6];  const float* b2 = (const float*)d_in[7];
    const float* g2 = (const float*)d_in[8];  const float* be2 = (const float*)d_in[9];
    const float* W3 = (const float*)d_in[10]; const float* b3 = (const float*)d_in[11];
    const float* g3 = (const float*)d_in[12]; const float* be3 = (const float*)d_in[13];
    const float* W4 = (const float*)d_in[14]; const float* b4 = (const float*)d_in[15];
    float* out = (float*)d_out;

    int E   = in_sizes[1] / 2;
    int H   = in_sizes[3];           // 96
    int Fin = in_sizes[2] / H;       // 32
    int N   = in_sizes[0] / Fin;     // 50000
    (void)n_in; (void)out_size;

    void *pA = nullptr, *pB = nullptr;
    cudaGetSymbolAddress(&pA, g_bufA);
    cudaGetSymbolAddress(&pB, g_bufB);
    float* bufA = (float*)pA;
    float* bufB = (float*)pB;

    int nb = cdiv(N, 256);
    int gemmGrid = cdiv(N, 32);
    int aggGrid  = cdiv(N, 8);

    // -------- per-call graph preprocessing: degrees, norms, CSR --------
    k_init     <<<nb, 256>>>(ei, N);
    k_count    <<<cdiv(E, 256), 256>>>(ei, E);
    k_dinv_bsum<<<nb, 256>>>(N);
    k_bscan    <<<1, 512>>>(nb);
    k_offsets  <<<nb, 256>>>(N);
    k_scatter  <<<cdiv(E, 256), 256>>>(ei, E);

    // -------- layer 1 --------
    k_agg4<<<cdiv(N, 32), 256>>>(x, bufA, N);
    k_gemm96<<<gemmGrid, 256>>>(bufA, W1, b1, bufB, N, Fin);
    k_bnfin<<<1, 96>>>(g1, be1, N);
    k_bnrelu<<<cdiv(N * 24, 256), 256>>>(bufB, bufB, N * 24);

    // -------- layer 2 --------
    k_agg24<<<aggGrid, 256>>>(bufB, bufA, N);
    k_gemm96<<<gemmGrid, 256>>>(bufA, W2, b2, bufB, N, 96);
    k_bnfin<<<1, 96>>>(g2, be2, N);
    k_bnrelu<<<cdiv(N * 24, 256), 256>>>(bufB, bufB, N * 24);

    // -------- layer 3 --------
    k_agg24<<<aggGrid, 256>>>(bufB, bufA, N);
    k_gemm96<<<gemmGrid, 256>>>(bufA, W3, b3, bufB, N, 96);
    k_bnfin<<<1, 96>>>(g3, be3, N);

    // -------- layer 4 --------
    k_gemm_out<<<cdiv(N, 16), 256>>>(bufB, W4, bufA, N);
    k_aggf<<<cdiv(N, 32), 256>>>(bufA, b4, out, N);
}